// round 1
// baseline (speedup 1.0000x reference)
#include <cuda_runtime.h>
#include <math.h>

// FFJORD: 2 chained fixed-step DOPRI5 integrations of a (64+1)->256->256->64 MLP field.
// One CTA integrates 16 batch rows end-to-end; everything stays in shared memory.
// fp32 throughout via packed fma.rn.f32x2 (sm_103a FFMA2: 2 FMAs/instr).

typedef unsigned long long u64;

#define Dd      64
#define Hh      256
#define MROWS   16      // batch rows per CTA (4096/16 = 256 CTAs, exact)
#define STR     18      // padded smem row stride in floats (even -> 8B aligned pairs)
#define NT      128     // threads per CTA
#define NSTEPS  16

// shared layout (floats):
//   sY  [64 ][STR]   current state (feature-major)
//   sZ  [65 ][STR]   stage input (state + time column at feature 64)
//   sH1 [256][STR]
//   sH2 [256][STR]
//   sK  [6][64][STR] RK stage derivatives k1..k6
#define SM_FLOATS ((Dd + (Dd+1) + Hh + Hh + 6*Dd) * STR)
#define SM_BYTES  (SM_FLOATS * 4)

struct FfjordParams {
    const float* W1[2]; const float* b1[2];
    const float* W2[2]; const float* b2[2];
    const float* W3[2]; const float* b3[2];
};

__device__ __forceinline__ u64 pack2(float lo, float hi) {
    u64 r;
    asm("mov.b64 %0, {%1, %2};" : "=l"(r)
        : "r"(__float_as_uint(lo)), "r"(__float_as_uint(hi)));
    return r;
}
__device__ __forceinline__ void fma2(u64& d, u64 a, u64 b) {
    asm("fma.rn.f32x2 %0, %1, %2, %3;" : "=l"(d) : "l"(a), "l"(b), "l"(d));
}
__device__ __forceinline__ float lo32(u64 v) { return __uint_as_float((unsigned)(v & 0xffffffffull)); }
__device__ __forceinline__ float hi32(u64 v) { return __uint_as_float((unsigned)(v >> 32)); }

// One dense layer for this CTA's 16-row tile.
// sA: [K][STR] feature-major activations. Output written [N][STR] feature-major.
// Thread (tcol = tid&31, r0 = (tid>>5)*4) computes cols {tcol + 32*cc} x rows [r0, r0+4).
template<int K, int N, bool TANH>
__device__ __forceinline__ void dense_layer(
    const float* __restrict__ W,      // [K][N] row-major
    const float* __restrict__ bias,   // [N]
    const float* __restrict__ sA,
    float*       __restrict__ sOut,
    int tcol, int r0)
{
    constexpr int NCC = N / 32;
    u64 acc[2][NCC];
#pragma unroll
    for (int cc = 0; cc < NCC; cc++) {
        float bb = __ldg(bias + tcol + 32 * cc);
        u64 bp = pack2(bb, bb);
        acc[0][cc] = bp;
        acc[1][cc] = bp;
    }

    const float* wrow = W + tcol;
#pragma unroll 4
    for (int k = 0; k < K; k++) {
        const float* ar = sA + k * STR + r0;
        u64 a0 = *(const u64*)(ar);       // rows r0, r0+1 (8B aligned: STR even, r0 mult of 4)
        u64 a1 = *(const u64*)(ar + 2);   // rows r0+2, r0+3
#pragma unroll
        for (int cc = 0; cc < NCC; cc++) {
            float wv = __ldg(wrow + 32 * cc);
            u64 wp = pack2(wv, wv);
            fma2(acc[0][cc], a0, wp);
            fma2(acc[1][cc], a1, wp);
        }
        wrow += N;
    }

#pragma unroll
    for (int cc = 0; cc < NCC; cc++) {
        int c = tcol + 32 * cc;
#pragma unroll
        for (int p = 0; p < 2; p++) {
            float v0 = lo32(acc[p][cc]);
            float v1 = hi32(acc[p][cc]);
            if (TANH) { v0 = tanhf(v0); v1 = tanhf(v1); }
            *(float2*)&sOut[c * STR + r0 + 2 * p] = make_float2(v0, v1);
        }
    }
}

// Butcher tableau (classic Dormand-Prince), stage coefficients a[s][l] and c[s].
__device__ const float DP_A[6][5] = {
    { 0.f, 0.f, 0.f, 0.f, 0.f },
    { 1.f/5.f, 0.f, 0.f, 0.f, 0.f },
    { 3.f/40.f, 9.f/40.f, 0.f, 0.f, 0.f },
    { 44.f/45.f, -56.f/15.f, 32.f/9.f, 0.f, 0.f },
    { 19372.f/6561.f, -25360.f/2187.f, 64448.f/6561.f, -212.f/729.f, 0.f },
    { 9017.f/3168.f, -355.f/33.f, 46732.f/5247.f, 49.f/176.f, -5103.f/18656.f },
};
__device__ const float DP_C[6] = { 0.f, 1.f/5.f, 3.f/10.f, 4.f/5.f, 8.f/9.f, 1.f };

__global__ void __launch_bounds__(NT)
ffjord_kernel(const float* __restrict__ x, float* __restrict__ out, FfjordParams P)
{
    extern __shared__ float sm[];
    float* sY  = sm;
    float* sZ  = sY + Dd * STR;
    float* sH1 = sZ + (Dd + 1) * STR;
    float* sH2 = sH1 + Hh * STR;
    float* sK  = sH2 + Hh * STR;   // [6][64][STR]

    const int tid  = threadIdx.x;
    const int tcol = tid & 31;
    const int r0   = (tid >> 5) * 4;
    const int rbase = blockIdx.x * MROWS;

    // Load x tile (coalesced global, transposed into feature-major smem)
    for (int i = tid; i < MROWS * Dd; i += NT) {
        int r = i / Dd, d = i % Dd;
        sY[d * STR + r] = x[(rbase + r) * Dd + d];
    }
    __syncthreads();

    const float h = 1.0f / 16.0f;

    for (int bij = 0; bij < 2; bij++) {
        const float* W1 = P.W1[bij]; const float* b1 = P.b1[bij];
        const float* W2 = P.W2[bij]; const float* b2 = P.b2[bij];
        const float* W3 = P.W3[bij]; const float* b3 = P.b3[bij];

        for (int step = 0; step < NSTEPS; step++) {
            float t0 = (float)step * h;

            for (int s = 0; s < 6; s++) {
                // Build stage input Z = y + h*sum_l a[s][l]*k_l ; Z[64] = t
                float tstage = t0 + DP_C[s] * h;
                for (int i = tid; i < (Dd + 1) * MROWS; i += NT) {
                    int d = i / MROWS, r = i % MROWS;
                    float z;
                    if (d == Dd) {
                        z = tstage;
                    } else {
                        z = sY[d * STR + r];
                        for (int l = 0; l < s; l++) {
                            float a = DP_A[s][l];
                            z += h * a * sK[(l * Dd + d) * STR + r];
                        }
                    }
                    sZ[d * STR + r] = z;
                }
                __syncthreads();

                dense_layer<Dd + 1, Hh, true >(W1, b1, sZ,  sH1, tcol, r0);
                __syncthreads();
                dense_layer<Hh,     Hh, true >(W2, b2, sH1, sH2, tcol, r0);
                __syncthreads();
                dense_layer<Hh,     Dd, false>(W3, b3, sH2, sK + s * Dd * STR, tcol, r0);
                __syncthreads();
            }

            // y += h * (b1*k1 + b3*k3 + b4*k4 + b5*k5 + b6*k6)   (b2 = 0)
            for (int i = tid; i < Dd * MROWS; i += NT) {
                int d = i / MROWS, r = i % MROWS;
                int o = d * STR + r;
                float acc = (35.f/384.f)    * sK[o]
                          + (500.f/1113.f)  * sK[(2*Dd)*STR + o]
                          + (125.f/192.f)   * sK[(3*Dd)*STR + o]
                          + (-2187.f/6784.f)* sK[(4*Dd)*STR + o]
                          + (11.f/84.f)     * sK[(5*Dd)*STR + o];
                sY[o] += h * acc;
            }
            __syncthreads();
        }
    }

    // Write result (coalesced)
    for (int i = tid; i < MROWS * Dd; i += NT) {
        int r = i / Dd, d = i % Dd;
        out[(rbase + r) * Dd + d] = sY[d * STR + r];
    }
}

extern "C" void kernel_launch(void* const* d_in, const int* in_sizes, int n_in,
                              void* d_out, int out_size)
{
    (void)in_sizes; (void)n_in; (void)out_size;
    const float* x = (const float*)d_in[0];

    FfjordParams P;
    P.W1[0] = (const float*)d_in[1];  P.b1[0] = (const float*)d_in[2];
    P.W2[0] = (const float*)d_in[3];  P.b2[0] = (const float*)d_in[4];
    P.W3[0] = (const float*)d_in[5];  P.b3[0] = (const float*)d_in[6];
    P.W1[1] = (const float*)d_in[7];  P.b1[1] = (const float*)d_in[8];
    P.W2[1] = (const float*)d_in[9];  P.b2[1] = (const float*)d_in[10];
    P.W3[1] = (const float*)d_in[11]; P.b3[1] = (const float*)d_in[12];

    static_assert(SM_BYTES < 100 * 1024, "smem budget");
    cudaFuncSetAttribute(ffjord_kernel, cudaFuncAttributeMaxDynamicSharedMemorySize, SM_BYTES);

    ffjord_kernel<<<4096 / MROWS, NT, SM_BYTES>>>(x, (float*)d_out, P);
}

// round 2
// speedup vs baseline: 1.9100x; 1.9100x over previous
#include <cuda_runtime.h>

// FFJORD: 2 chained fixed-step DOPRI5 integrations of a (64+1)->256->256->64 MLP field.
// One CTA integrates 16 batch rows end-to-end in shared memory.
// fp32 via packed fma.rn.f32x2; weights streamed from L1/L2 with distance-2
// register prefetch (LDG.128), activations via broadcast LDS.128.

typedef unsigned long long u64;

#define Dd      64
#define Hh      256
#define MROWS   16      // batch rows per CTA (4096/16 = 256 CTAs)
#define STR     20      // padded smem row stride (multiple of 4 -> 16B aligned)
#define NT      128
#define NSTEPS  16

// smem floats: sY[64] sZ[65] sH1[256] sH2[256] sK[6*64], each x STR
#define SM_FLOATS ((Dd + (Dd+1) + Hh + Hh + 6*Dd) * STR)
#define SM_BYTES  (SM_FLOATS * 4)   // 82 000 B -> 2 CTAs/SM

struct FfjordParams {
    const float* W1[2]; const float* b1[2];
    const float* W2[2]; const float* b2[2];
    const float* W3[2]; const float* b3[2];
};

__device__ __forceinline__ u64 dup2(float v) {
    u64 r; asm("mov.b64 %0, {%1, %1};" : "=l"(r) : "r"(__float_as_uint(v)));
    return r;
}
__device__ __forceinline__ u64 mk2(float lo, float hi) {
    u64 r; asm("mov.b64 %0, {%1, %2};" : "=l"(r)
               : "r"(__float_as_uint(lo)), "r"(__float_as_uint(hi)));
    return r;
}
__device__ __forceinline__ void fma2(u64& d, u64 a, u64 b) {
    asm("fma.rn.f32x2 %0, %1, %2, %3;" : "=l"(d) : "l"(a), "l"(b), "l"(d));
}
__device__ __forceinline__ float lo32(u64 v){ return __uint_as_float((unsigned)v); }
__device__ __forceinline__ float hi32(u64 v){ return __uint_as_float((unsigned)(v>>32)); }

// branch-free tanh: 1 - 2/(1+e^{2x});  2 MUFU + few FMA, ~1e-6 accurate
__device__ __forceinline__ float fast_tanh(float x) {
    float u = __expf(2.0f * x);
    return 1.0f - __fdividef(2.0f, u + 1.0f);
}

// Dormand-Prince tableau
__constant__ float DP_A[6][5] = {
    { 0.f, 0.f, 0.f, 0.f, 0.f },
    { 1.f/5.f, 0.f, 0.f, 0.f, 0.f },
    { 3.f/40.f, 9.f/40.f, 0.f, 0.f, 0.f },
    { 44.f/45.f, -56.f/15.f, 32.f/9.f, 0.f, 0.f },
    { 19372.f/6561.f, -25360.f/2187.f, 64448.f/6561.f, -212.f/729.f, 0.f },
    { 9017.f/3168.f, -355.f/33.f, 46732.f/5247.f, 49.f/176.f, -5103.f/18656.f },
};
__constant__ float DP_C[6] = { 0.f, 1.f/5.f, 3.f/10.f, 4.f/5.f, 8.f/9.f, 1.f };

// N=256 dense layer. W: [K][256] row-major. Thread (tcol, r0) computes
// cols {4*tcol..+3} and {128+4*tcol..+3} for rows r0..r0+3.
// acc[g][cp][r] u64 = (out[c], out[c+1]) with c = 4*tcol+128g+2cp, row r0+r.
template<int K, bool TANH>
__device__ __forceinline__ void dense256(
    const float* __restrict__ W, const float* __restrict__ bias,
    const float* __restrict__ sA, float* __restrict__ sOut,
    int tcol, int r0)
{
    u64 acc[2][2][4];
#pragma unroll
    for (int g = 0; g < 2; g++) {
        float4 bb = *(const float4*)(bias + 4*tcol + 128*g);
        u64 b01 = mk2(bb.x, bb.y), b23 = mk2(bb.z, bb.w);
#pragma unroll
        for (int r = 0; r < 4; r++) { acc[g][0][r] = b01; acc[g][1][r] = b23; }
    }

    const float* w0 = W + 4*tcol;
    const float* w1 = W + 4*tcol + 128;

    float4 wbuf[2][2];       // [k parity][group] — distance-2 prefetch
    float4 abuf[2];          // distance-1 activation prefetch
    wbuf[0][0] = *(const float4*)(w0);
    wbuf[0][1] = *(const float4*)(w1);
    wbuf[1][0] = *(const float4*)(w0 + Hh);
    wbuf[1][1] = *(const float4*)(w1 + Hh);
    abuf[0]    = *(const float4*)(sA + r0);

#pragma unroll 2
    for (int k = 0; k < K; k++) {
        float4 a4 = abuf[k & 1];
        if (k + 1 < K) abuf[(k + 1) & 1] = *(const float4*)(sA + (k + 1) * STR + r0);

        float4 wA = wbuf[k & 1][0];
        float4 wB = wbuf[k & 1][1];
        if (k + 2 < K) {
            wbuf[k & 1][0] = *(const float4*)(w0 + (k + 2) * Hh);
            wbuf[k & 1][1] = *(const float4*)(w1 + (k + 2) * Hh);
        }

        u64 wp00 = mk2(wA.x, wA.y), wp01 = mk2(wA.z, wA.w);
        u64 wp10 = mk2(wB.x, wB.y), wp11 = mk2(wB.z, wB.w);
        u64 ar[4] = { dup2(a4.x), dup2(a4.y), dup2(a4.z), dup2(a4.w) };
#pragma unroll
        for (int r = 0; r < 4; r++) {
            fma2(acc[0][0][r], ar[r], wp00);
            fma2(acc[0][1][r], ar[r], wp01);
            fma2(acc[1][0][r], ar[r], wp10);
            fma2(acc[1][1][r], ar[r], wp11);
        }
    }

#pragma unroll
    for (int g = 0; g < 2; g++) {
        int cbase = 4*tcol + 128*g;
#pragma unroll
        for (int cp = 0; cp < 2; cp++) {
            float v0[4], v1[4];
#pragma unroll
            for (int r = 0; r < 4; r++) {
                v0[r] = lo32(acc[g][cp][r]);
                v1[r] = hi32(acc[g][cp][r]);
                if (TANH) { v0[r] = fast_tanh(v0[r]); v1[r] = fast_tanh(v1[r]); }
            }
            *(float4*)(sOut + (cbase + 2*cp    ) * STR + r0) = make_float4(v0[0],v0[1],v0[2],v0[3]);
            *(float4*)(sOut + (cbase + 2*cp + 1) * STR + r0) = make_float4(v1[0],v1[1],v1[2],v1[3]);
        }
    }
}

// N=64 output layer (K=256). Thread computes cols {2*tcol, 2*tcol+1}, rows r0..r0+3.
__device__ __forceinline__ void dense64(
    const float* __restrict__ W, const float* __restrict__ bias,
    const float* __restrict__ sA, float* __restrict__ sOut,
    int tcol, int r0)
{
    u64 acc[4];
    {
        float2 bb = *(const float2*)(bias + 2*tcol);
        u64 bp = mk2(bb.x, bb.y);
#pragma unroll
        for (int r = 0; r < 4; r++) acc[r] = bp;
    }
    const float* w0 = W + 2*tcol;

    float2 wbuf[2];
    float4 abuf[2];
    wbuf[0] = *(const float2*)(w0);
    wbuf[1] = *(const float2*)(w0 + Dd);
    abuf[0] = *(const float4*)(sA + r0);

#pragma unroll 2
    for (int k = 0; k < Hh; k++) {
        float4 a4 = abuf[k & 1];
        if (k + 1 < Hh) abuf[(k + 1) & 1] = *(const float4*)(sA + (k + 1) * STR + r0);
        float2 wv = wbuf[k & 1];
        if (k + 2 < Hh) wbuf[k & 1] = *(const float2*)(w0 + (k + 2) * Dd);

        u64 wp = mk2(wv.x, wv.y);
        fma2(acc[0], dup2(a4.x), wp);
        fma2(acc[1], dup2(a4.y), wp);
        fma2(acc[2], dup2(a4.z), wp);
        fma2(acc[3], dup2(a4.w), wp);
    }

    float v0[4], v1[4];
#pragma unroll
    for (int r = 0; r < 4; r++) { v0[r] = lo32(acc[r]); v1[r] = hi32(acc[r]); }
    *(float4*)(sOut + (2*tcol    ) * STR + r0) = make_float4(v0[0],v0[1],v0[2],v0[3]);
    *(float4*)(sOut + (2*tcol + 1) * STR + r0) = make_float4(v1[0],v1[1],v1[2],v1[3]);
}

__global__ void __launch_bounds__(NT, 2)
ffjord_kernel(const float* __restrict__ x, float* __restrict__ out, FfjordParams P)
{
    extern __shared__ float sm[];
    float* sY  = sm;
    float* sZ  = sY + Dd * STR;
    float* sH1 = sZ + (Dd + 1) * STR;
    float* sH2 = sH1 + Hh * STR;
    float* sK  = sH2 + Hh * STR;   // [6][64][STR]

    const int tid   = threadIdx.x;
    const int tcol  = tid & 31;
    const int r0    = (tid >> 5) * 4;
    const int rbase = blockIdx.x * MROWS;

    for (int i = tid; i < MROWS * Dd; i += NT) {
        int r = i >> 6, d = i & 63;
        sY[d * STR + r] = x[(rbase + r) * Dd + d];
    }
    __syncthreads();

    const float h = 1.0f / 16.0f;

    for (int bij = 0; bij < 2; bij++) {
        const float* W1 = P.W1[bij]; const float* b1 = P.b1[bij];
        const float* W2 = P.W2[bij]; const float* b2 = P.b2[bij];
        const float* W3 = P.W3[bij]; const float* b3 = P.b3[bij];

        for (int step = 0; step < NSTEPS; step++) {
            float t0 = (float)step * h;

            for (int s = 0; s < 6; s++) {
                float tstage = t0 + DP_C[s] * h;
                // Z = y + h * sum_l a[s][l] * k_l ; Z[64][*] = tstage
                for (int i = tid; i < (Dd + 1) * MROWS; i += NT) {
                    int d = i >> 4, r = i & 15;
                    float z;
                    if (d == Dd) {
                        z = tstage;
                    } else {
                        z = sY[d * STR + r];
                        for (int l = 0; l < s; l++)
                            z += (h * DP_A[s][l]) * sK[(l * Dd + d) * STR + r];
                    }
                    sZ[d * STR + r] = z;
                }
                __syncthreads();

                dense256<Dd + 1, true>(W1, b1, sZ,  sH1, tcol, r0);
                __syncthreads();
                dense256<Hh,     true>(W2, b2, sH1, sH2, tcol, r0);
                __syncthreads();
                dense64(W3, b3, sH2, sK + s * Dd * STR, tcol, r0);
                __syncthreads();
            }

            for (int i = tid; i < Dd * MROWS; i += NT) {
                int d = i >> 4, r = i & 15;
                int o = d * STR + r;
                float acc = (35.f/384.f)     * sK[o]
                          + (500.f/1113.f)   * sK[(2*Dd)*STR + o]
                          + (125.f/192.f)    * sK[(3*Dd)*STR + o]
                          + (-2187.f/6784.f) * sK[(4*Dd)*STR + o]
                          + (11.f/84.f)      * sK[(5*Dd)*STR + o];
                sY[o] += h * acc;
            }
            __syncthreads();
        }
    }

    for (int i = tid; i < MROWS * Dd; i += NT) {
        int r = i >> 6, d = i & 63;
        out[(rbase + r) * Dd + d] = sY[d * STR + r];
    }
}

extern "C" void kernel_launch(void* const* d_in, const int* in_sizes, int n_in,
                              void* d_out, int out_size)
{
    (void)in_sizes; (void)n_in; (void)out_size;
    const float* x = (const float*)d_in[0];

    FfjordParams P;
    P.W1[0] = (const float*)d_in[1];  P.b1[0] = (const float*)d_in[2];
    P.W2[0] = (const float*)d_in[3];  P.b2[0] = (const float*)d_in[4];
    P.W3[0] = (const float*)d_in[5];  P.b3[0] = (const float*)d_in[6];
    P.W1[1] = (const float*)d_in[7];  P.b1[1] = (const float*)d_in[8];
    P.W2[1] = (const float*)d_in[9];  P.b2[1] = (const float*)d_in[10];
    P.W3[1] = (const float*)d_in[11]; P.b3[1] = (const float*)d_in[12];

    static_assert(SM_BYTES <= 160 * 1024, "smem budget");
    cudaFuncSetAttribute(ffjord_kernel, cudaFuncAttributeMaxDynamicSharedMemorySize, SM_BYTES);

    ffjord_kernel<<<4096 / MROWS, NT, SM_BYTES>>>(x, (float*)d_out, P);
}

// round 3
// speedup vs baseline: 2.9342x; 1.5363x over previous
#include <cuda_runtime.h>

// FFJORD: 2 chained fixed-step DOPRI5 integrations of a (64+1)->256->256->64 MLP.
// One CTA integrates 16 batch rows end-to-end. fp32 via fma.rn.f32x2 with
// zero-MOV operand formation: weights arrive as natural reg pairs (LDG.128),
// activations stored DUPLICATED in smem so LDS.128 yields (a,a) broadcast pairs.
// RK stage derivatives live in global scratch to keep L1D alive for weight dedup.

typedef unsigned long long u64;

#define Dd     64
#define Hh     256
#define MROWS  16
#define STRD   36      // duplicated-activation stride (2*MROWS+4, multiple of 4)
#define STRY   16      // sY / gK stride
#define NT     128
#define NSTEPS 16
#define NCTAS  (4096 / MROWS)   // 256

// smem: sZd[(Dd+1)][STRD] + sH1d[Hh][STRD] + sH2d[Hh][STRD] + sY[Dd][STRY]
#define SM_FLOATS ((Dd + 1 + Hh + Hh) * STRD + Dd * STRY)
#define SM_BYTES  (SM_FLOATS * 4)    // 87,184 B -> 2 CTAs/SM, L1D ~54 KB

// RK stage derivatives k1..k6, per CTA: [6][Dd][STRY]
__device__ float gK[NCTAS][6 * Dd * STRY];

struct FfjordParams {
    const float* W1[2]; const float* b1[2];
    const float* W2[2]; const float* b2[2];
    const float* W3[2]; const float* b3[2];
};

__device__ __forceinline__ u64 mk2(float lo, float hi) {
    u64 r; asm("mov.b64 %0, {%1, %2};" : "=l"(r)
               : "r"(__float_as_uint(lo)), "r"(__float_as_uint(hi)));
    return r;
}
__device__ __forceinline__ void fma2(u64& d, u64 a, u64 b) {
    asm("fma.rn.f32x2 %0, %1, %2, %3;" : "=l"(d) : "l"(a), "l"(b), "l"(d));
}
__device__ __forceinline__ float lo32(u64 v){ return __uint_as_float((unsigned)v); }
__device__ __forceinline__ float hi32(u64 v){ return __uint_as_float((unsigned)(v>>32)); }

__device__ __forceinline__ void ldg2(u64& a, u64& b, const float* p) {
    asm("ld.global.nc.v2.u64 {%0, %1}, [%2];" : "=l"(a), "=l"(b) : "l"(p));
}
__device__ __forceinline__ u64 ldg1(const float* p) {
    u64 r; asm("ld.global.nc.u64 %0, [%1];" : "=l"(r) : "l"(p)); return r;
}

__device__ __forceinline__ float fast_tanh(float x) {
    float u = __expf(2.0f * x);
    return 1.0f - __fdividef(2.0f, u + 1.0f);
}

__constant__ float DP_A[6][5] = {
    { 0.f, 0.f, 0.f, 0.f, 0.f },
    { 1.f/5.f, 0.f, 0.f, 0.f, 0.f },
    { 3.f/40.f, 9.f/40.f, 0.f, 0.f, 0.f },
    { 44.f/45.f, -56.f/15.f, 32.f/9.f, 0.f, 0.f },
    { 19372.f/6561.f, -25360.f/2187.f, 64448.f/6561.f, -212.f/729.f, 0.f },
    { 9017.f/3168.f, -355.f/33.f, 46732.f/5247.f, 49.f/176.f, -5103.f/18656.f },
};
__constant__ float DP_C[6] = { 0.f, 1.f/5.f, 3.f/10.f, 4.f/5.f, 8.f/9.f, 1.f };

// N=256 layer. Thread (lane, r0=4*warp): cols {4*lane..+3, 128+4*lane..+3},
// rows r0..r0+3. Weight pairs natural from LDG.128; activation (a,a) pairs
// natural from duplicated-layout LDS.128. Output written duplicated.
template<int K, bool TANH>
__device__ __forceinline__ void dense256(
    const float* __restrict__ W, const float* __restrict__ bias,
    const float* __restrict__ sAd, float* __restrict__ sOutd,
    int lane, int r0)
{
    u64 acc[4][2][2];   // [row][group][colpair]
    {
        float4 b0 = *(const float4*)(bias + 4*lane);
        float4 b1 = *(const float4*)(bias + 128 + 4*lane);
        u64 p00 = mk2(b0.x,b0.y), p01 = mk2(b0.z,b0.w);
        u64 p10 = mk2(b1.x,b1.y), p11 = mk2(b1.z,b1.w);
#pragma unroll
        for (int r = 0; r < 4; r++) {
            acc[r][0][0] = p00; acc[r][0][1] = p01;
            acc[r][1][0] = p10; acc[r][1][1] = p11;
        }
    }

    const float* w0 = W + 4*lane;
    const float* w1 = w0 + 128;
    const float* aP = sAd + 2*r0;

    u64 wb[4][2][2];               // distance-4 weight ring
#pragma unroll
    for (int s = 0; s < 4; s++) {
        ldg2(wb[s][0][0], wb[s][0][1], w0 + s*Hh);
        ldg2(wb[s][1][0], wb[s][1][1], w1 + s*Hh);
    }
    u64 ab[2][4];                  // distance-1 activation dup pairs (4 rows)
    {
        ulonglong2 t0 = *(const ulonglong2*)(aP);
        ulonglong2 t1 = *(const ulonglong2*)(aP + 4);
        ab[0][0] = t0.x; ab[0][1] = t0.y; ab[0][2] = t1.x; ab[0][3] = t1.y;
    }

    int k = 0;
#pragma unroll 4
    for (; k < K - 4; k++) {
        const int slot = k & 3, pb = k & 1;
        u64 w00 = wb[slot][0][0], w01 = wb[slot][0][1];
        u64 w10 = wb[slot][1][0], w11 = wb[slot][1][1];
        ldg2(wb[slot][0][0], wb[slot][0][1], w0 + (k+4)*Hh);
        ldg2(wb[slot][1][0], wb[slot][1][1], w1 + (k+4)*Hh);
        u64 a0 = ab[pb][0], a1 = ab[pb][1], a2 = ab[pb][2], a3 = ab[pb][3];
        {
            const float* ap1 = aP + (k+1)*STRD;
            ulonglong2 t0 = *(const ulonglong2*)(ap1);
            ulonglong2 t1 = *(const ulonglong2*)(ap1 + 4);
            ab[pb^1][0] = t0.x; ab[pb^1][1] = t0.y;
            ab[pb^1][2] = t1.x; ab[pb^1][3] = t1.y;
        }
        fma2(acc[0][0][0], a0, w00); fma2(acc[0][0][1], a0, w01);
        fma2(acc[0][1][0], a0, w10); fma2(acc[0][1][1], a0, w11);
        fma2(acc[1][0][0], a1, w00); fma2(acc[1][0][1], a1, w01);
        fma2(acc[1][1][0], a1, w10); fma2(acc[1][1][1], a1, w11);
        fma2(acc[2][0][0], a2, w00); fma2(acc[2][0][1], a2, w01);
        fma2(acc[2][1][0], a2, w10); fma2(acc[2][1][1], a2, w11);
        fma2(acc[3][0][0], a3, w00); fma2(acc[3][0][1], a3, w01);
        fma2(acc[3][1][0], a3, w10); fma2(acc[3][1][1], a3, w11);
    }
#pragma unroll
    for (; k < K; k++) {           // tail: no weight prefetch
        const int slot = k & 3, pb = k & 1;
        u64 w00 = wb[slot][0][0], w01 = wb[slot][0][1];
        u64 w10 = wb[slot][1][0], w11 = wb[slot][1][1];
        u64 a0 = ab[pb][0], a1 = ab[pb][1], a2 = ab[pb][2], a3 = ab[pb][3];
        if (k + 1 < K) {
            const float* ap1 = aP + (k+1)*STRD;
            ulonglong2 t0 = *(const ulonglong2*)(ap1);
            ulonglong2 t1 = *(const ulonglong2*)(ap1 + 4);
            ab[pb^1][0] = t0.x; ab[pb^1][1] = t0.y;
            ab[pb^1][2] = t1.x; ab[pb^1][3] = t1.y;
        }
        fma2(acc[0][0][0], a0, w00); fma2(acc[0][0][1], a0, w01);
        fma2(acc[0][1][0], a0, w10); fma2(acc[0][1][1], a0, w11);
        fma2(acc[1][0][0], a1, w00); fma2(acc[1][0][1], a1, w01);
        fma2(acc[1][1][0], a1, w10); fma2(acc[1][1][1], a1, w11);
        fma2(acc[2][0][0], a2, w00); fma2(acc[2][0][1], a2, w01);
        fma2(acc[2][1][0], a2, w10); fma2(acc[2][1][1], a2, w11);
        fma2(acc[3][0][0], a3, w00); fma2(acc[3][0][1], a3, w01);
        fma2(acc[3][1][0], a3, w10); fma2(acc[3][1][1], a3, w11);
    }

#pragma unroll
    for (int g = 0; g < 2; g++)
#pragma unroll
    for (int p = 0; p < 2; p++) {
        int c = 4*lane + 128*g + 2*p;
        float l0 = lo32(acc[0][g][p]), l1 = lo32(acc[1][g][p]);
        float l2 = lo32(acc[2][g][p]), l3 = lo32(acc[3][g][p]);
        float h0 = hi32(acc[0][g][p]), h1 = hi32(acc[1][g][p]);
        float h2 = hi32(acc[2][g][p]), h3 = hi32(acc[3][g][p]);
        if (TANH) {
            l0 = fast_tanh(l0); l1 = fast_tanh(l1); l2 = fast_tanh(l2); l3 = fast_tanh(l3);
            h0 = fast_tanh(h0); h1 = fast_tanh(h1); h2 = fast_tanh(h2); h3 = fast_tanh(h3);
        }
        float* o0 = sOutd + c*STRD + 2*r0;
        float* o1 = sOutd + (c+1)*STRD + 2*r0;
        *(float4*)(o0)     = make_float4(l0,l0,l1,l1);
        *(float4*)(o0 + 4) = make_float4(l2,l2,l3,l3);
        *(float4*)(o1)     = make_float4(h0,h0,h1,h1);
        *(float4*)(o1 + 4) = make_float4(h2,h2,h3,h3);
    }
}

// N=64 output layer (K=256). Thread: cols (2*lane, 2*lane+1), rows r0..r0+3.
// Writes plain [col][STRY] layout into global stage buffer.
__device__ __forceinline__ void dense64out(
    const float* __restrict__ W, const float* __restrict__ bias,
    const float* __restrict__ sAd, float* __restrict__ gOut,
    int lane, int r0)
{
    u64 acc[4];
    {
        float2 bb = *(const float2*)(bias + 2*lane);
        u64 bp = mk2(bb.x, bb.y);
#pragma unroll
        for (int r = 0; r < 4; r++) acc[r] = bp;
    }
    const float* w0 = W + 2*lane;
    const float* aP = sAd + 2*r0;

    u64 wb[4];
#pragma unroll
    for (int s = 0; s < 4; s++) wb[s] = ldg1(w0 + s*Dd);
    u64 ab[2][4];
    {
        ulonglong2 t0 = *(const ulonglong2*)(aP);
        ulonglong2 t1 = *(const ulonglong2*)(aP + 4);
        ab[0][0] = t0.x; ab[0][1] = t0.y; ab[0][2] = t1.x; ab[0][3] = t1.y;
    }

    int k = 0;
#pragma unroll 4
    for (; k < Hh - 4; k++) {
        const int slot = k & 3, pb = k & 1;
        u64 w = wb[slot];
        wb[slot] = ldg1(w0 + (k+4)*Dd);
        u64 a0 = ab[pb][0], a1 = ab[pb][1], a2 = ab[pb][2], a3 = ab[pb][3];
        {
            const float* ap1 = aP + (k+1)*STRD;
            ulonglong2 t0 = *(const ulonglong2*)(ap1);
            ulonglong2 t1 = *(const ulonglong2*)(ap1 + 4);
            ab[pb^1][0] = t0.x; ab[pb^1][1] = t0.y;
            ab[pb^1][2] = t1.x; ab[pb^1][3] = t1.y;
        }
        fma2(acc[0], a0, w); fma2(acc[1], a1, w);
        fma2(acc[2], a2, w); fma2(acc[3], a3, w);
    }
#pragma unroll
    for (; k < Hh; k++) {
        const int slot = k & 3, pb = k & 1;
        u64 w = wb[slot];
        u64 a0 = ab[pb][0], a1 = ab[pb][1], a2 = ab[pb][2], a3 = ab[pb][3];
        if (k + 1 < Hh) {
            const float* ap1 = aP + (k+1)*STRD;
            ulonglong2 t0 = *(const ulonglong2*)(ap1);
            ulonglong2 t1 = *(const ulonglong2*)(ap1 + 4);
            ab[pb^1][0] = t0.x; ab[pb^1][1] = t0.y;
            ab[pb^1][2] = t1.x; ab[pb^1][3] = t1.y;
        }
        fma2(acc[0], a0, w); fma2(acc[1], a1, w);
        fma2(acc[2], a2, w); fma2(acc[3], a3, w);
    }

    *(float4*)(gOut + (2*lane    )*STRY + r0) =
        make_float4(lo32(acc[0]), lo32(acc[1]), lo32(acc[2]), lo32(acc[3]));
    *(float4*)(gOut + (2*lane + 1)*STRY + r0) =
        make_float4(hi32(acc[0]), hi32(acc[1]), hi32(acc[2]), hi32(acc[3]));
}

__global__ void __launch_bounds__(NT, 2)
ffjord_kernel(const float* __restrict__ x, float* __restrict__ out, FfjordParams P)
{
    extern __shared__ float sm[];
    float* sZd  = sm;                          // (Dd+1) x STRD, duplicated
    float* sH1d = sZd + (Dd + 1) * STRD;       // Hh x STRD, duplicated
    float* sH2d = sH1d + Hh * STRD;            // Hh x STRD, duplicated
    float* sY   = sH2d + Hh * STRD;            // Dd x STRY

    const int tid   = threadIdx.x;
    const int lane  = tid & 31;
    const int r0    = (tid >> 5) * 4;
    const int rbase = blockIdx.x * MROWS;
    float* gk = gK[blockIdx.x];                // [6][Dd][STRY]

    for (int i = tid; i < MROWS * Dd; i += NT) {
        int r = i >> 6, d = i & 63;
        sY[d * STRY + r] = x[(rbase + r) * Dd + d];
    }
    __syncthreads();

    const float h = 1.0f / 16.0f;

    for (int bij = 0; bij < 2; bij++) {
        const float* W1 = P.W1[bij]; const float* b1 = P.b1[bij];
        const float* W2 = P.W2[bij]; const float* b2 = P.b2[bij];
        const float* W3 = P.W3[bij]; const float* b3 = P.b3[bij];

        for (int step = 0; step < NSTEPS; step++) {
            float t0 = (float)step * h;

            for (int s = 0; s < 6; s++) {
                float tstage = t0 + DP_C[s] * h;
                float ha[5];
#pragma unroll
                for (int l = 0; l < 5; l++) ha[l] = h * DP_A[s][l];

                // Z = y + sum_{l<s} ha[l]*k_l ; Z[Dd][*] = tstage (dup layout)
                for (int i = tid; i < (Dd + 1) * MROWS; i += NT) {
                    int d = i >> 4, r = i & 15;
                    float z;
                    if (d == Dd) {
                        z = tstage;
                    } else {
                        z = sY[d * STRY + r];
#pragma unroll
                        for (int l = 0; l < 5; l++)
                            if (l < s) z += ha[l] * gk[(l * Dd + d) * STRY + r];
                    }
                    *(float2*)(sZd + d * STRD + 2 * r) = make_float2(z, z);
                }
                __syncthreads();

                dense256<Dd + 1, true>(W1, b1, sZd,  sH1d, lane, r0);
                __syncthreads();
                dense256<Hh,     true>(W2, b2, sH1d, sH2d, lane, r0);
                __syncthreads();
                dense64out(W3, b3, sH2d, gk + s * Dd * STRY, lane, r0);
                __syncthreads();
            }

            for (int i = tid; i < Dd * MROWS; i += NT) {
                int d = i >> 4, r = i & 15;
                int o = d * STRY + r;
                float acc = (35.f/384.f)     * gk[o]
                          + (500.f/1113.f)   * gk[(2*Dd)*STRY + o]
                          + (125.f/192.f)    * gk[(3*Dd)*STRY + o]
                          + (-2187.f/6784.f) * gk[(4*Dd)*STRY + o]
                          + (11.f/84.f)      * gk[(5*Dd)*STRY + o];
                sY[o] += h * acc;
            }
            __syncthreads();
        }
    }

    for (int i = tid; i < MROWS * Dd; i += NT) {
        int r = i >> 6, d = i & 63;
        out[(rbase + r) * Dd + d] = sY[d * STRY + r];
    }
}

extern "C" void kernel_launch(void* const* d_in, const int* in_sizes, int n_in,
                              void* d_out, int out_size)
{
    (void)in_sizes; (void)n_in; (void)out_size;
    const float* x = (const float*)d_in[0];

    FfjordParams P;
    P.W1[0] = (const float*)d_in[1];  P.b1[0] = (const float*)d_in[2];
    P.W2[0] = (const float*)d_in[3];  P.b2[0] = (const float*)d_in[4];
    P.W3[0] = (const float*)d_in[5];  P.b3[0] = (const float*)d_in[6];
    P.W1[1] = (const float*)d_in[7];  P.b1[1] = (const float*)d_in[8];
    P.W2[1] = (const float*)d_in[9];  P.b2[1] = (const float*)d_in[10];
    P.W3[1] = (const float*)d_in[11]; P.b3[1] = (const float*)d_in[12];

    static_assert(SM_BYTES <= 110 * 1024, "smem budget (2 CTAs/SM + L1D)");
    cudaFuncSetAttribute(ffjord_kernel, cudaFuncAttributeMaxDynamicSharedMemorySize, SM_BYTES);

    ffjord_kernel<<<NCTAS, NT, SM_BYTES>>>(x, (float*)d_out, P);
}

// round 4
// speedup vs baseline: 3.2401x; 1.1042x over previous
#include <cuda_runtime.h>

// FFJORD: 2 chained fixed-step DOPRI5 integrations of a (64+1)->256->256->64 MLP.
// One CTA integrates 16 batch rows end-to-end. fp32 via fma.rn.f32x2 with
// zero-MOV operand formation (dup-layout activations, natural LDG.128 weight pairs).
// R4: 256 threads (8 warps = 4 rowgroups x 2 colgroups), depth-8 weight prefetch
// ring to cover L2 latency; 2 CTAs/SM -> 16 warps/SM.

typedef unsigned long long u64;

#define Dd     64
#define Hh     256
#define MROWS  16
#define STRD   36      // duplicated-activation stride (2*MROWS+4)
#define STRY   16
#define NT     256
#define NSTEPS 16
#define NCTAS  (4096 / MROWS)   // 256
#define RD     8       // weight prefetch ring depth

#define SM_FLOATS ((Dd + 1 + Hh + Hh) * STRD + Dd * STRY)
#define SM_BYTES  (SM_FLOATS * 4)    // 87,184 B -> 2 CTAs/SM

__device__ float gK[NCTAS][6 * Dd * STRY];

struct FfjordParams {
    const float* W1[2]; const float* b1[2];
    const float* W2[2]; const float* b2[2];
    const float* W3[2]; const float* b3[2];
};

__device__ __forceinline__ u64 mk2(float lo, float hi) {
    u64 r; asm("mov.b64 %0, {%1, %2};" : "=l"(r)
               : "r"(__float_as_uint(lo)), "r"(__float_as_uint(hi)));
    return r;
}
__device__ __forceinline__ void fma2(u64& d, u64 a, u64 b) {
    asm("fma.rn.f32x2 %0, %1, %2, %3;" : "=l"(d) : "l"(a), "l"(b), "l"(d));
}
__device__ __forceinline__ float lo32(u64 v){ return __uint_as_float((unsigned)v); }
__device__ __forceinline__ float hi32(u64 v){ return __uint_as_float((unsigned)(v>>32)); }

__device__ __forceinline__ void ldg2(u64& a, u64& b, const float* p) {
    asm("ld.global.nc.v2.u64 {%0, %1}, [%2];" : "=l"(a), "=l"(b) : "l"(p));
}
__device__ __forceinline__ u64 ldg1(const float* p) {
    u64 r; asm("ld.global.nc.u64 %0, [%1];" : "=l"(r) : "l"(p)); return r;
}

__device__ __forceinline__ float fast_tanh(float x) {
    float u = __expf(2.0f * x);
    return 1.0f - __fdividef(2.0f, u + 1.0f);
}

__constant__ float DP_A[6][5] = {
    { 0.f, 0.f, 0.f, 0.f, 0.f },
    { 1.f/5.f, 0.f, 0.f, 0.f, 0.f },
    { 3.f/40.f, 9.f/40.f, 0.f, 0.f, 0.f },
    { 44.f/45.f, -56.f/15.f, 32.f/9.f, 0.f, 0.f },
    { 19372.f/6561.f, -25360.f/2187.f, 64448.f/6561.f, -212.f/729.f, 0.f },
    { 9017.f/3168.f, -355.f/33.f, 46732.f/5247.f, 49.f/176.f, -5103.f/18656.f },
};
__constant__ float DP_C[6] = { 0.f, 1.f/5.f, 3.f/10.f, 4.f/5.f, 8.f/9.f, 1.f };

// N=256 layer, warp owns ONE 4-col group: cols 128*g + 4*lane .. +3, rows r0..r0+3.
// acc[r][p] = (out[c+2p], out[c+2p+1]) for row r0+r.
template<int K, bool TANH>
__device__ __forceinline__ void dense256(
    const float* __restrict__ W, const float* __restrict__ bias,
    const float* __restrict__ sAd, float* __restrict__ sOutd,
    int lane, int g, int r0)
{
    u64 acc[4][2];
    {
        float4 b = *(const float4*)(bias + 128*g + 4*lane);
        u64 p0 = mk2(b.x, b.y), p1 = mk2(b.z, b.w);
#pragma unroll
        for (int r = 0; r < 4; r++) { acc[r][0] = p0; acc[r][1] = p1; }
    }

    const float* w0 = W + 128*g + 4*lane;
    const float* aP = sAd + 2*r0;

    u64 wb[RD][2];                    // depth-8 weight ring (LDG.128 each)
#pragma unroll
    for (int s = 0; s < RD; s++) ldg2(wb[s][0], wb[s][1], w0 + s*Hh);

    u64 ab[2][4];                     // dist-1 activation dup pairs (4 rows)
    {
        ulonglong2 t0 = *(const ulonglong2*)(aP);
        ulonglong2 t1 = *(const ulonglong2*)(aP + 4);
        ab[0][0] = t0.x; ab[0][1] = t0.y; ab[0][2] = t1.x; ab[0][3] = t1.y;
    }

    int k = 0;
#pragma unroll 8
    for (; k < K - RD; k++) {
        const int slot = k & (RD-1), pb = k & 1;
        u64 wA = wb[slot][0], wB = wb[slot][1];
        ldg2(wb[slot][0], wb[slot][1], w0 + (k + RD)*Hh);
        u64 a0 = ab[pb][0], a1 = ab[pb][1], a2 = ab[pb][2], a3 = ab[pb][3];
        {
            const float* ap1 = aP + (k+1)*STRD;
            ulonglong2 t0 = *(const ulonglong2*)(ap1);
            ulonglong2 t1 = *(const ulonglong2*)(ap1 + 4);
            ab[pb^1][0] = t0.x; ab[pb^1][1] = t0.y;
            ab[pb^1][2] = t1.x; ab[pb^1][3] = t1.y;
        }
        fma2(acc[0][0], a0, wA); fma2(acc[0][1], a0, wB);
        fma2(acc[1][0], a1, wA); fma2(acc[1][1], a1, wB);
        fma2(acc[2][0], a2, wA); fma2(acc[2][1], a2, wB);
        fma2(acc[3][0], a3, wA); fma2(acc[3][1], a3, wB);
    }
#pragma unroll
    for (; k < K; k++) {              // tail: ring already holds k..K-1
        const int slot = k & (RD-1), pb = k & 1;
        u64 wA = wb[slot][0], wB = wb[slot][1];
        u64 a0 = ab[pb][0], a1 = ab[pb][1], a2 = ab[pb][2], a3 = ab[pb][3];
        if (k + 1 < K) {
            const float* ap1 = aP + (k+1)*STRD;
            ulonglong2 t0 = *(const ulonglong2*)(ap1);
            ulonglong2 t1 = *(const ulonglong2*)(ap1 + 4);
            ab[pb^1][0] = t0.x; ab[pb^1][1] = t0.y;
            ab[pb^1][2] = t1.x; ab[pb^1][3] = t1.y;
        }
        fma2(acc[0][0], a0, wA); fma2(acc[0][1], a0, wB);
        fma2(acc[1][0], a1, wA); fma2(acc[1][1], a1, wB);
        fma2(acc[2][0], a2, wA); fma2(acc[2][1], a2, wB);
        fma2(acc[3][0], a3, wA); fma2(acc[3][1], a3, wB);
    }

#pragma unroll
    for (int p = 0; p < 2; p++) {
        int c = 128*g + 4*lane + 2*p;
        float l0 = lo32(acc[0][p]), l1 = lo32(acc[1][p]);
        float l2 = lo32(acc[2][p]), l3 = lo32(acc[3][p]);
        float h0 = hi32(acc[0][p]), h1 = hi32(acc[1][p]);
        float h2 = hi32(acc[2][p]), h3 = hi32(acc[3][p]);
        if (TANH) {
            l0 = fast_tanh(l0); l1 = fast_tanh(l1); l2 = fast_tanh(l2); l3 = fast_tanh(l3);
            h0 = fast_tanh(h0); h1 = fast_tanh(h1); h2 = fast_tanh(h2); h3 = fast_tanh(h3);
        }
        float* o0 = sOutd + c*STRD + 2*r0;
        float* o1 = sOutd + (c+1)*STRD + 2*r0;
        *(float4*)(o0)     = make_float4(l0,l0,l1,l1);
        *(float4*)(o0 + 4) = make_float4(l2,l2,l3,l3);
        *(float4*)(o1)     = make_float4(h0,h0,h1,h1);
        *(float4*)(o1 + 4) = make_float4(h2,h2,h3,h3);
    }
}

// N=64 output layer (K=256), 8 warps: warp w -> rows (2w, 2w+1);
// thread: cols (2*lane, 2*lane+1) x 2 rows.
__device__ __forceinline__ void dense64out(
    const float* __restrict__ W, const float* __restrict__ bias,
    const float* __restrict__ sAd, float* __restrict__ gOut,
    int lane, int r0d)
{
    u64 acc[2];
    {
        float2 bb = *(const float2*)(bias + 2*lane);
        u64 bp = mk2(bb.x, bb.y);
        acc[0] = bp; acc[1] = bp;
    }
    const float* w0 = W + 2*lane;
    const float* aP = sAd + 2*r0d;

    u64 wb[RD];
#pragma unroll
    for (int s = 0; s < RD; s++) wb[s] = ldg1(w0 + s*Dd);
    u64 ab[2][2];
    {
        ulonglong2 t = *(const ulonglong2*)(aP);
        ab[0][0] = t.x; ab[0][1] = t.y;
    }

    int k = 0;
#pragma unroll 8
    for (; k < Hh - RD; k++) {
        const int slot = k & (RD-1), pb = k & 1;
        u64 w = wb[slot];
        wb[slot] = ldg1(w0 + (k + RD)*Dd);
        u64 a0 = ab[pb][0], a1 = ab[pb][1];
        {
            ulonglong2 t = *(const ulonglong2*)(aP + (k+1)*STRD);
            ab[pb^1][0] = t.x; ab[pb^1][1] = t.y;
        }
        fma2(acc[0], a0, w); fma2(acc[1], a1, w);
    }
#pragma unroll
    for (; k < Hh; k++) {
        const int slot = k & (RD-1), pb = k & 1;
        u64 w = wb[slot];
        u64 a0 = ab[pb][0], a1 = ab[pb][1];
        if (k + 1 < Hh) {
            ulonglong2 t = *(const ulonglong2*)(aP + (k+1)*STRD);
            ab[pb^1][0] = t.x; ab[pb^1][1] = t.y;
        }
        fma2(acc[0], a0, w); fma2(acc[1], a1, w);
    }

    *(float2*)(gOut + (2*lane    )*STRY + r0d) = make_float2(lo32(acc[0]), lo32(acc[1]));
    *(float2*)(gOut + (2*lane + 1)*STRY + r0d) = make_float2(hi32(acc[0]), hi32(acc[1]));
}

__global__ void __launch_bounds__(NT, 2)
ffjord_kernel(const float* __restrict__ x, float* __restrict__ out, FfjordParams P)
{
    extern __shared__ float sm[];
    float* sZd  = sm;                          // (Dd+1) x STRD, duplicated
    float* sH1d = sZd + (Dd + 1) * STRD;
    float* sH2d = sH1d + Hh * STRD;
    float* sY   = sH2d + Hh * STRD;            // Dd x STRY

    const int tid   = threadIdx.x;
    const int lane  = tid & 31;
    const int w     = tid >> 5;                // 0..7
    const int r0    = (w & 3) * 4;             // rowgroup for dense256
    const int g     = w >> 2;                  // colgroup for dense256
    const int r0d   = w * 2;                   // rowgroup for dense64
    const int rbase = blockIdx.x * MROWS;
    float* gk = gK[blockIdx.x];

    for (int i = tid; i < MROWS * Dd; i += NT) {
        int r = i >> 6, d = i & 63;
        sY[d * STRY + r] = x[(rbase + r) * Dd + d];
    }
    __syncthreads();

    const float h = 1.0f / 16.0f;

    for (int bij = 0; bij < 2; bij++) {
        const float* W1 = P.W1[bij]; const float* b1 = P.b1[bij];
        const float* W2 = P.W2[bij]; const float* b2 = P.b2[bij];
        const float* W3 = P.W3[bij]; const float* b3 = P.b3[bij];

        for (int step = 0; step < NSTEPS; step++) {
            float t0 = (float)step * h;

            for (int s = 0; s < 6; s++) {
                float tstage = t0 + DP_C[s] * h;
                float ha[5];
#pragma unroll
                for (int l = 0; l < 5; l++) ha[l] = h * DP_A[s][l];

                for (int i = tid; i < (Dd + 1) * MROWS; i += NT) {
                    int d = i >> 4, r = i & 15;
                    float z;
                    if (d == Dd) {
                        z = tstage;
                    } else {
                        z = sY[d * STRY + r];
#pragma unroll
                        for (int l = 0; l < 5; l++)
                            if (l < s) z += ha[l] * gk[(l * Dd + d) * STRY + r];
                    }
                    *(float2*)(sZd + d * STRD + 2 * r) = make_float2(z, z);
                }
                __syncthreads();

                dense256<Dd + 1, true>(W1, b1, sZd,  sH1d, lane, g, r0);
                __syncthreads();
                dense256<Hh,     true>(W2, b2, sH1d, sH2d, lane, g, r0);
                __syncthreads();
                dense64out(W3, b3, sH2d, gk + s * Dd * STRY, lane, r0d);
                __syncthreads();
            }

            for (int i = tid; i < Dd * MROWS; i += NT) {
                int d = i >> 4, r = i & 15;
                int o = d * STRY + r;
                float acc = (35.f/384.f)     * gk[o]
                          + (500.f/1113.f)   * gk[(2*Dd)*STRY + o]
                          + (125.f/192.f)    * gk[(3*Dd)*STRY + o]
                          + (-2187.f/6784.f) * gk[(4*Dd)*STRY + o]
                          + (11.f/84.f)      * gk[(5*Dd)*STRY + o];
                sY[o] += h * acc;
            }
            __syncthreads();
        }
    }

    for (int i = tid; i < MROWS * Dd; i += NT) {
        int r = i >> 6, d = i & 63;
        out[(rbase + r) * Dd + d] = sY[d * STRY + r];
    }
}

extern "C" void kernel_launch(void* const* d_in, const int* in_sizes, int n_in,
                              void* d_out, int out_size)
{
    (void)in_sizes; (void)n_in; (void)out_size;
    const float* x = (const float*)d_in[0];

    FfjordParams P;
    P.W1[0] = (const float*)d_in[1];  P.b1[0] = (const float*)d_in[2];
    P.W2[0] = (const float*)d_in[3];  P.b2[0] = (const float*)d_in[4];
    P.W3[0] = (const float*)d_in[5];  P.b3[0] = (const float*)d_in[6];
    P.W1[1] = (const float*)d_in[7];  P.b1[1] = (const float*)d_in[8];
    P.W2[1] = (const float*)d_in[9];  P.b2[1] = (const float*)d_in[10];
    P.W3[1] = (const float*)d_in[11]; P.b3[1] = (const float*)d_in[12];

    static_assert(SM_BYTES <= 113 * 1024, "smem budget (2 CTAs/SM)");
    cudaFuncSetAttribute(ffjord_kernel, cudaFuncAttributeMaxDynamicSharedMemorySize, SM_BYTES);

    ffjord_kernel<<<NCTAS, NT, SM_BYTES>>>(x, (float*)d_out, P);
}

// round 5
// speedup vs baseline: 3.7951x; 1.1713x over previous
#include <cuda_runtime.h>

// FFJORD: 2 chained fixed-step DOPRI5 integrations of a (64+1)->256->256->64 MLP.
// One CTA integrates 16 batch rows. fp32 via fma.rn.f32x2, zero-MOV operands
// (dup-layout activations, natural LDG.128 weight pairs).
// R5: fat thread tiles — 8 rows x 4 cols per thread (NT=128, 4 warps =
// 2 rowgroups x 2 colgroups) to halve L1 wavefronts per FLOP; depth-8 ring.

typedef unsigned long long u64;

#define Dd     64
#define Hh     256
#define MROWS  16
#define STRD   36      // duplicated-activation stride
#define STRY   16
#define NT     128
#define NSTEPS 16
#define NCTAS  (4096 / MROWS)   // 256
#define RD     8       // weight prefetch ring depth

#define SM_FLOATS ((Dd + 1 + Hh + Hh) * STRD + Dd * STRY)
#define SM_BYTES  (SM_FLOATS * 4)    // 87,184 B -> 2 CTAs/SM

__device__ float gK[NCTAS][6 * Dd * STRY];

struct FfjordParams {
    const float* W1[2]; const float* b1[2];
    const float* W2[2]; const float* b2[2];
    const float* W3[2]; const float* b3[2];
};

__device__ __forceinline__ u64 mk2(float lo, float hi) {
    u64 r; asm("mov.b64 %0, {%1, %2};" : "=l"(r)
               : "r"(__float_as_uint(lo)), "r"(__float_as_uint(hi)));
    return r;
}
__device__ __forceinline__ void fma2(u64& d, u64 a, u64 b) {
    asm("fma.rn.f32x2 %0, %1, %2, %3;" : "=l"(d) : "l"(a), "l"(b), "l"(d));
}
__device__ __forceinline__ float lo32(u64 v){ return __uint_as_float((unsigned)v); }
__device__ __forceinline__ float hi32(u64 v){ return __uint_as_float((unsigned)(v>>32)); }

__device__ __forceinline__ void ldg2(u64& a, u64& b, const float* p) {
    asm("ld.global.nc.v2.u64 {%0, %1}, [%2];" : "=l"(a), "=l"(b) : "l"(p));
}
__device__ __forceinline__ u64 ldg1(const float* p) {
    u64 r; asm("ld.global.nc.u64 %0, [%1];" : "=l"(r) : "l"(p)); return r;
}

__device__ __forceinline__ float fast_tanh(float x) {
    float u = __expf(2.0f * x);
    return 1.0f - __fdividef(2.0f, u + 1.0f);
}

__constant__ float DP_A[6][5] = {
    { 0.f, 0.f, 0.f, 0.f, 0.f },
    { 1.f/5.f, 0.f, 0.f, 0.f, 0.f },
    { 3.f/40.f, 9.f/40.f, 0.f, 0.f, 0.f },
    { 44.f/45.f, -56.f/15.f, 32.f/9.f, 0.f, 0.f },
    { 19372.f/6561.f, -25360.f/2187.f, 64448.f/6561.f, -212.f/729.f, 0.f },
    { 9017.f/3168.f, -355.f/33.f, 46732.f/5247.f, 49.f/176.f, -5103.f/18656.f },
};
__constant__ float DP_C[6] = { 0.f, 1.f/5.f, 3.f/10.f, 4.f/5.f, 8.f/9.f, 1.f };

// N=256 layer. 4 warps: warp w -> rowgroup rg=w&1 (rows 8*rg..+7),
// colgroup g=w>>1 (cols 128*g + 4*lane..+3).
// acc[r][p] = (out[c+2p], out[c+2p+1]) for row r0+r, r<8.
template<int K, bool TANH>
__device__ __forceinline__ void dense256(
    const float* __restrict__ W, const float* __restrict__ bias,
    const float* __restrict__ sAd, float* __restrict__ sOutd,
    int lane, int g, int r0)
{
    u64 acc[8][2];
    {
        float4 b = *(const float4*)(bias + 128*g + 4*lane);
        u64 p0 = mk2(b.x, b.y), p1 = mk2(b.z, b.w);
#pragma unroll
        for (int r = 0; r < 8; r++) { acc[r][0] = p0; acc[r][1] = p1; }
    }

    const float* w0 = W + 128*g + 4*lane;
    const float* aP = sAd + 2*r0;      // 8 dup pairs = 64 B per k

    u64 wb[RD][2];                     // depth-8 weight ring (LDG.128)
#pragma unroll
    for (int s = 0; s < RD; s++) ldg2(wb[s][0], wb[s][1], w0 + s*Hh);

    u64 ab[2][8];                      // dist-1 activation dup pairs (8 rows)
#pragma unroll
    for (int q = 0; q < 4; q++) {
        ulonglong2 t = *(const ulonglong2*)(aP + 4*q);
        ab[0][2*q] = t.x; ab[0][2*q+1] = t.y;
    }

    int k = 0;
#pragma unroll 8
    for (; k < K - RD; k++) {
        const int slot = k & (RD-1), pb = k & 1;
        u64 wA = wb[slot][0], wB = wb[slot][1];
        ldg2(wb[slot][0], wb[slot][1], w0 + (k + RD)*Hh);
        {
            const float* ap1 = aP + (k+1)*STRD;
#pragma unroll
            for (int q = 0; q < 4; q++) {
                ulonglong2 t = *(const ulonglong2*)(ap1 + 4*q);
                ab[pb^1][2*q] = t.x; ab[pb^1][2*q+1] = t.y;
            }
        }
#pragma unroll
        for (int r = 0; r < 8; r++) {
            fma2(acc[r][0], ab[pb][r], wA);
            fma2(acc[r][1], ab[pb][r], wB);
        }
    }
#pragma unroll
    for (; k < K; k++) {               // tail: ring holds k..K-1
        const int slot = k & (RD-1), pb = k & 1;
        u64 wA = wb[slot][0], wB = wb[slot][1];
        if (k + 1 < K) {
            const float* ap1 = aP + (k+1)*STRD;
#pragma unroll
            for (int q = 0; q < 4; q++) {
                ulonglong2 t = *(const ulonglong2*)(ap1 + 4*q);
                ab[pb^1][2*q] = t.x; ab[pb^1][2*q+1] = t.y;
            }
        }
#pragma unroll
        for (int r = 0; r < 8; r++) {
            fma2(acc[r][0], ab[pb][r], wA);
            fma2(acc[r][1], ab[pb][r], wB);
        }
    }

#pragma unroll
    for (int p = 0; p < 2; p++) {
        int c = 128*g + 4*lane + 2*p;
        float lv[8], hv[8];
#pragma unroll
        for (int r = 0; r < 8; r++) {
            lv[r] = lo32(acc[r][p]); hv[r] = hi32(acc[r][p]);
            if (TANH) { lv[r] = fast_tanh(lv[r]); hv[r] = fast_tanh(hv[r]); }
        }
        float* o0 = sOutd + c*STRD + 2*r0;
        float* o1 = sOutd + (c+1)*STRD + 2*r0;
#pragma unroll
        for (int q = 0; q < 4; q++) {
            *(float4*)(o0 + 4*q) = make_float4(lv[2*q], lv[2*q], lv[2*q+1], lv[2*q+1]);
            *(float4*)(o1 + 4*q) = make_float4(hv[2*q], hv[2*q], hv[2*q+1], hv[2*q+1]);
        }
    }
}

// N=64 output layer (K=256), 4 warps: warp w -> rows 4w..4w+3;
// thread: cols (2*lane, 2*lane+1) x 4 rows.
__device__ __forceinline__ void dense64out(
    const float* __restrict__ W, const float* __restrict__ bias,
    const float* __restrict__ sAd, float* __restrict__ gOut,
    int lane, int r0d)
{
    u64 acc[4];
    {
        float2 bb = *(const float2*)(bias + 2*lane);
        u64 bp = mk2(bb.x, bb.y);
#pragma unroll
        for (int r = 0; r < 4; r++) acc[r] = bp;
    }
    const float* w0 = W + 2*lane;
    const float* aP = sAd + 2*r0d;

    u64 wb[RD];
#pragma unroll
    for (int s = 0; s < RD; s++) wb[s] = ldg1(w0 + s*Dd);
    u64 ab[2][4];
    {
        ulonglong2 t0 = *(const ulonglong2*)(aP);
        ulonglong2 t1 = *(const ulonglong2*)(aP + 4);
        ab[0][0] = t0.x; ab[0][1] = t0.y; ab[0][2] = t1.x; ab[0][3] = t1.y;
    }

    int k = 0;
#pragma unroll 8
    for (; k < Hh - RD; k++) {
        const int slot = k & (RD-1), pb = k & 1;
        u64 w = wb[slot];
        wb[slot] = ldg1(w0 + (k + RD)*Dd);
        {
            const float* ap1 = aP + (k+1)*STRD;
            ulonglong2 t0 = *(const ulonglong2*)(ap1);
            ulonglong2 t1 = *(const ulonglong2*)(ap1 + 4);
            ab[pb^1][0] = t0.x; ab[pb^1][1] = t0.y;
            ab[pb^1][2] = t1.x; ab[pb^1][3] = t1.y;
        }
        fma2(acc[0], ab[pb][0], w); fma2(acc[1], ab[pb][1], w);
        fma2(acc[2], ab[pb][2], w); fma2(acc[3], ab[pb][3], w);
    }
#pragma unroll
    for (; k < Hh; k++) {
        const int slot = k & (RD-1), pb = k & 1;
        u64 w = wb[slot];
        if (k + 1 < Hh) {
            const float* ap1 = aP + (k+1)*STRD;
            ulonglong2 t0 = *(const ulonglong2*)(ap1);
            ulonglong2 t1 = *(const ulonglong2*)(ap1 + 4);
            ab[pb^1][0] = t0.x; ab[pb^1][1] = t0.y;
            ab[pb^1][2] = t1.x; ab[pb^1][3] = t1.y;
        }
        fma2(acc[0], ab[pb][0], w); fma2(acc[1], ab[pb][1], w);
        fma2(acc[2], ab[pb][2], w); fma2(acc[3], ab[pb][3], w);
    }

    *(float4*)(gOut + (2*lane    )*STRY + r0d) =
        make_float4(lo32(acc[0]), lo32(acc[1]), lo32(acc[2]), lo32(acc[3]));
    *(float4*)(gOut + (2*lane + 1)*STRY + r0d) =
        make_float4(hi32(acc[0]), hi32(acc[1]), hi32(acc[2]), hi32(acc[3]));
}

__global__ void __launch_bounds__(NT, 2)
ffjord_kernel(const float* __restrict__ x, float* __restrict__ out, FfjordParams P)
{
    extern __shared__ float sm[];
    float* sZd  = sm;                          // (Dd+1) x STRD, duplicated
    float* sH1d = sZd + (Dd + 1) * STRD;
    float* sH2d = sH1d + Hh * STRD;
    float* sY   = sH2d + Hh * STRD;            // Dd x STRY

    const int tid   = threadIdx.x;
    const int lane  = tid & 31;
    const int w     = tid >> 5;                // 0..3
    const int r0    = (w & 1) * 8;             // rowgroup for dense256 (8 rows)
    const int g     = w >> 1;                  // colgroup for dense256
    const int r0d   = w * 4;                   // rowgroup for dense64 (4 rows)
    const int rbase = blockIdx.x * MROWS;
    float* gk = gK[blockIdx.x];

    for (int i = tid; i < MROWS * Dd; i += NT) {
        int r = i >> 6, d = i & 63;
        sY[d * STRY + r] = x[(rbase + r) * Dd + d];
    }
    __syncthreads();

    const float h = 1.0f / 16.0f;

    for (int bij = 0; bij < 2; bij++) {
        const float* W1 = P.W1[bij]; const float* b1 = P.b1[bij];
        const float* W2 = P.W2[bij]; const float* b2 = P.b2[bij];
        const float* W3 = P.W3[bij]; const float* b3 = P.b3[bij];

        for (int step = 0; step < NSTEPS; step++) {
            float t0 = (float)step * h;

            for (int s = 0; s < 6; s++) {
                float tstage = t0 + DP_C[s] * h;
                float ha[5];
#pragma unroll
                for (int l = 0; l < 5; l++) ha[l] = h * DP_A[s][l];

                for (int i = tid; i < (Dd + 1) * MROWS; i += NT) {
                    int d = i >> 4, r = i & 15;
                    float z;
                    if (d == Dd) {
                        z = tstage;
                    } else {
                        z = sY[d * STRY + r];
#pragma unroll
                        for (int l = 0; l < 5; l++)
                            if (l < s) z += ha[l] * gk[(l * Dd + d) * STRY + r];
                    }
                    *(float2*)(sZd + d * STRD + 2 * r) = make_float2(z, z);
                }
                __syncthreads();

                dense256<Dd + 1, true>(W1, b1, sZd,  sH1d, lane, g, r0);
                __syncthreads();
                dense256<Hh,     true>(W2, b2, sH1d, sH2d, lane, g, r0);
                __syncthreads();
                dense64out(W3, b3, sH2d, gk + s * Dd * STRY, lane, r0d);
                __syncthreads();
            }

            for (int i = tid; i < Dd * MROWS; i += NT) {
                int d = i >> 4, r = i & 15;
                int o = d * STRY + r;
                float acc = (35.f/384.f)     * gk[o]
                          + (500.f/1113.f)   * gk[(2*Dd)*STRY + o]
                          + (125.f/192.f)    * gk[(3*Dd)*STRY + o]
                          + (-2187.f/6784.f) * gk[(4*Dd)*STRY + o]
                          + (11.f/84.f)      * gk[(5*Dd)*STRY + o];
                sY[o] += h * acc;
            }
            __syncthreads();
        }
    }

    for (int i = tid; i < MROWS * Dd; i += NT) {
        int r = i >> 6, d = i & 63;
        out[(rbase + r) * Dd + d] = sY[d * STRY + r];
    }
}

extern "C" void kernel_launch(void* const* d_in, const int* in_sizes, int n_in,
                              void* d_out, int out_size)
{
    (void)in_sizes; (void)n_in; (void)out_size;
    const float* x = (const float*)d_in[0];

    FfjordParams P;
    P.W1[0] = (const float*)d_in[1];  P.b1[0] = (const float*)d_in[2];
    P.W2[0] = (const float*)d_in[3];  P.b2[0] = (const float*)d_in[4];
    P.W3[0] = (const float*)d_in[5];  P.b3[0] = (const float*)d_in[6];
    P.W1[1] = (const float*)d_in[7];  P.b1[1] = (const float*)d_in[8];
    P.W2[1] = (const float*)d_in[9];  P.b2[1] = (const float*)d_in[10];
    P.W3[1] = (const float*)d_in[11]; P.b3[1] = (const float*)d_in[12];

    static_assert(SM_BYTES <= 113 * 1024, "smem budget (2 CTAs/SM)");
    cudaFuncSetAttribute(ffjord_kernel, cudaFuncAttributeMaxDynamicSharedMemorySize, SM_BYTES);

    ffjord_kernel<<<NCTAS, NT, SM_BYTES>>>(x, (float*)d_out, P);
}

// round 6
// speedup vs baseline: 3.8635x; 1.0180x over previous
#include <cuda_runtime.h>

// FFJORD: 2 chained fixed-step DOPRI5 integrations of a (64+1)->256->256->64 MLP.
// One CTA integrates 16 batch rows. fp32 via fma.rn.f32x2, zero-MOV operands
// (dup-layout activations, natural LDG.128 weight pairs).
// R6: 3 CTAs/SM (12 warps) via smem diet — H2 stored non-duplicated (only the
// small dense64 layer reads it); launch_bounds(128,3) caps regs at 170.

typedef unsigned long long u64;

#define Dd     64
#define Hh     256
#define MROWS  16
#define STRD   36      // duplicated-activation stride (floats)
#define STRH2  20      // non-dup H2 stride (floats; 80 B = 16B-aligned rows)
#define STRY   16
#define NT     128
#define NSTEPS 16
#define NCTAS  (4096 / MROWS)   // 256
#define RD     8       // weight prefetch ring depth

// smem: sZd[(Dd+1)][STRD] + sH1d[Hh][STRD] + sH2[Hh][STRH2] + sY[Dd][STRY]
#define SM_FLOATS ((Dd + 1 + Hh) * STRD + Hh * STRH2 + Dd * STRY)
#define SM_BYTES  (SM_FLOATS * 4)    // 70,800 B -> 3 CTAs/SM (212.4 KB)

__device__ float gK[NCTAS][6 * Dd * STRY];

struct FfjordParams {
    const float* W1[2]; const float* b1[2];
    const float* W2[2]; const float* b2[2];
    const float* W3[2]; const float* b3[2];
};

__device__ __forceinline__ u64 mk2(float lo, float hi) {
    u64 r; asm("mov.b64 %0, {%1, %2};" : "=l"(r)
               : "r"(__float_as_uint(lo)), "r"(__float_as_uint(hi)));
    return r;
}
__device__ __forceinline__ u64 dup2(float v) {
    u64 r; asm("mov.b64 %0, {%1, %1};" : "=l"(r) : "r"(__float_as_uint(v)));
    return r;
}
__device__ __forceinline__ void fma2(u64& d, u64 a, u64 b) {
    asm("fma.rn.f32x2 %0, %1, %2, %3;" : "=l"(d) : "l"(a), "l"(b), "l"(d));
}
__device__ __forceinline__ float lo32(u64 v){ return __uint_as_float((unsigned)v); }
__device__ __forceinline__ float hi32(u64 v){ return __uint_as_float((unsigned)(v>>32)); }

__device__ __forceinline__ void ldg2(u64& a, u64& b, const float* p) {
    asm("ld.global.nc.v2.u64 {%0, %1}, [%2];" : "=l"(a), "=l"(b) : "l"(p));
}
__device__ __forceinline__ u64 ldg1(const float* p) {
    u64 r; asm("ld.global.nc.u64 %0, [%1];" : "=l"(r) : "l"(p)); return r;
}

__device__ __forceinline__ float fast_tanh(float x) {
    float u = __expf(2.0f * x);
    return 1.0f - __fdividef(2.0f, u + 1.0f);
}

__constant__ float DP_A[6][5] = {
    { 0.f, 0.f, 0.f, 0.f, 0.f },
    { 1.f/5.f, 0.f, 0.f, 0.f, 0.f },
    { 3.f/40.f, 9.f/40.f, 0.f, 0.f, 0.f },
    { 44.f/45.f, -56.f/15.f, 32.f/9.f, 0.f, 0.f },
    { 19372.f/6561.f, -25360.f/2187.f, 64448.f/6561.f, -212.f/729.f, 0.f },
    { 9017.f/3168.f, -355.f/33.f, 46732.f/5247.f, 49.f/176.f, -5103.f/18656.f },
};
__constant__ float DP_C[6] = { 0.f, 1.f/5.f, 3.f/10.f, 4.f/5.f, 8.f/9.f, 1.f };

// N=256 layer. 4 warps: rowgroup rg=w&1 (rows 8*rg..+7), colgroup g=w>>1
// (cols 128*g + 4*lane..+3). DUPOUT: write duplicated (stride STRD) or plain
// (stride STRH2).
template<int K, bool TANH, bool DUPOUT>
__device__ __forceinline__ void dense256(
    const float* __restrict__ W, const float* __restrict__ bias,
    const float* __restrict__ sAd, float* __restrict__ sOut,
    int lane, int g, int r0)
{
    u64 acc[8][2];
    {
        float4 b = *(const float4*)(bias + 128*g + 4*lane);
        u64 p0 = mk2(b.x, b.y), p1 = mk2(b.z, b.w);
#pragma unroll
        for (int r = 0; r < 8; r++) { acc[r][0] = p0; acc[r][1] = p1; }
    }

    const float* w0 = W + 128*g + 4*lane;
    const float* aP = sAd + 2*r0;

    u64 wb[RD][2];
#pragma unroll
    for (int s = 0; s < RD; s++) ldg2(wb[s][0], wb[s][1], w0 + s*Hh);

    u64 ab[2][8];
#pragma unroll
    for (int q = 0; q < 4; q++) {
        ulonglong2 t = *(const ulonglong2*)(aP + 4*q);
        ab[0][2*q] = t.x; ab[0][2*q+1] = t.y;
    }

    int k = 0;
#pragma unroll 8
    for (; k < K - RD; k++) {
        const int slot = k & (RD-1), pb = k & 1;
        u64 wA = wb[slot][0], wB = wb[slot][1];
        ldg2(wb[slot][0], wb[slot][1], w0 + (k + RD)*Hh);
        {
            const float* ap1 = aP + (k+1)*STRD;
#pragma unroll
            for (int q = 0; q < 4; q++) {
                ulonglong2 t = *(const ulonglong2*)(ap1 + 4*q);
                ab[pb^1][2*q] = t.x; ab[pb^1][2*q+1] = t.y;
            }
        }
#pragma unroll
        for (int r = 0; r < 8; r++) {
            fma2(acc[r][0], ab[pb][r], wA);
            fma2(acc[r][1], ab[pb][r], wB);
        }
    }
#pragma unroll
    for (; k < K; k++) {
        const int slot = k & (RD-1), pb = k & 1;
        u64 wA = wb[slot][0], wB = wb[slot][1];
        if (k + 1 < K) {
            const float* ap1 = aP + (k+1)*STRD;
#pragma unroll
            for (int q = 0; q < 4; q++) {
                ulonglong2 t = *(const ulonglong2*)(ap1 + 4*q);
                ab[pb^1][2*q] = t.x; ab[pb^1][2*q+1] = t.y;
            }
        }
#pragma unroll
        for (int r = 0; r < 8; r++) {
            fma2(acc[r][0], ab[pb][r], wA);
            fma2(acc[r][1], ab[pb][r], wB);
        }
    }

#pragma unroll
    for (int p = 0; p < 2; p++) {
        int c = 128*g + 4*lane + 2*p;
        float lv[8], hv[8];
#pragma unroll
        for (int r = 0; r < 8; r++) {
            lv[r] = lo32(acc[r][p]); hv[r] = hi32(acc[r][p]);
            if (TANH) { lv[r] = fast_tanh(lv[r]); hv[r] = fast_tanh(hv[r]); }
        }
        if (DUPOUT) {
            float* o0 = sOut + c*STRD + 2*r0;
            float* o1 = sOut + (c+1)*STRD + 2*r0;
#pragma unroll
            for (int q = 0; q < 4; q++) {
                *(float4*)(o0 + 4*q) = make_float4(lv[2*q], lv[2*q], lv[2*q+1], lv[2*q+1]);
                *(float4*)(o1 + 4*q) = make_float4(hv[2*q], hv[2*q], hv[2*q+1], hv[2*q+1]);
            }
        } else {
            float* o0 = sOut + c*STRH2 + r0;
            float* o1 = sOut + (c+1)*STRH2 + r0;
            *(float4*)(o0)     = make_float4(lv[0], lv[1], lv[2], lv[3]);
            *(float4*)(o0 + 4) = make_float4(lv[4], lv[5], lv[6], lv[7]);
            *(float4*)(o1)     = make_float4(hv[0], hv[1], hv[2], hv[3]);
            *(float4*)(o1 + 4) = make_float4(hv[4], hv[5], hv[6], hv[7]);
        }
    }
}

// N=64 output layer (K=256). 4 warps: warp w -> rows 4w..4w+3;
// thread: cols (2*lane, 2*lane+1) x 4 rows. Reads NON-dup H2 (stride STRH2).
__device__ __forceinline__ void dense64out(
    const float* __restrict__ W, const float* __restrict__ bias,
    const float* __restrict__ sA, float* __restrict__ gOut,
    int lane, int r0d)
{
    u64 acc[4];
    {
        float2 bb = *(const float2*)(bias + 2*lane);
        u64 bp = mk2(bb.x, bb.y);
#pragma unroll
        for (int r = 0; r < 4; r++) acc[r] = bp;
    }
    const float* w0 = W + 2*lane;
    const float* aP = sA + r0d;

    u64 wb[RD];
#pragma unroll
    for (int s = 0; s < RD; s++) wb[s] = ldg1(w0 + s*Dd);
    float4 af[2];
    af[0] = *(const float4*)(aP);

    int k = 0;
#pragma unroll 8
    for (; k < Hh - RD; k++) {
        const int slot = k & (RD-1), pb = k & 1;
        u64 w = wb[slot];
        wb[slot] = ldg1(w0 + (k + RD)*Dd);
        float4 a4 = af[pb];
        af[pb^1] = *(const float4*)(aP + (k+1)*STRH2);
        fma2(acc[0], dup2(a4.x), w); fma2(acc[1], dup2(a4.y), w);
        fma2(acc[2], dup2(a4.z), w); fma2(acc[3], dup2(a4.w), w);
    }
#pragma unroll
    for (; k < Hh; k++) {
        const int slot = k & (RD-1), pb = k & 1;
        u64 w = wb[slot];
        float4 a4 = af[pb];
        if (k + 1 < Hh) af[pb^1] = *(const float4*)(aP + (k+1)*STRH2);
        fma2(acc[0], dup2(a4.x), w); fma2(acc[1], dup2(a4.y), w);
        fma2(acc[2], dup2(a4.z), w); fma2(acc[3], dup2(a4.w), w);
    }

    *(float4*)(gOut + (2*lane    )*STRY + r0d) =
        make_float4(lo32(acc[0]), lo32(acc[1]), lo32(acc[2]), lo32(acc[3]));
    *(float4*)(gOut + (2*lane + 1)*STRY + r0d) =
        make_float4(hi32(acc[0]), hi32(acc[1]), hi32(acc[2]), hi32(acc[3]));
}

__global__ void __launch_bounds__(NT, 3)
ffjord_kernel(const float* __restrict__ x, float* __restrict__ out, FfjordParams P)
{
    extern __shared__ float sm[];
    float* sZd  = sm;                          // (Dd+1) x STRD, duplicated
    float* sH1d = sZd + (Dd + 1) * STRD;       // Hh x STRD, duplicated
    float* sH2  = sH1d + Hh * STRD;            // Hh x STRH2, plain
    float* sY   = sH2 + Hh * STRH2;            // Dd x STRY

    const int tid   = threadIdx.x;
    const int lane  = tid & 31;
    const int w     = tid >> 5;                // 0..3
    const int r0    = (w & 1) * 8;             // dense256 rowgroup (8 rows)
    const int g     = w >> 1;                  // dense256 colgroup
    const int r0d   = w * 4;                   // dense64 rowgroup (4 rows)
    const int rbase = blockIdx.x * MROWS;
    float* gk = gK[blockIdx.x];

    for (int i = tid; i < MROWS * Dd; i += NT) {
        int r = i >> 6, d = i & 63;
        sY[d * STRY + r] = x[(rbase + r) * Dd + d];
    }
    __syncthreads();

    const float h = 1.0f / 16.0f;

    for (int bij = 0; bij < 2; bij++) {
        const float* W1 = P.W1[bij]; const float* b1 = P.b1[bij];
        const float* W2 = P.W2[bij]; const float* b2 = P.b2[bij];
        const float* W3 = P.W3[bij]; const float* b3 = P.b3[bij];

        for (int step = 0; step < NSTEPS; step++) {
            float t0 = (float)step * h;

            for (int s = 0; s < 6; s++) {
                float tstage = t0 + DP_C[s] * h;
                float ha[5];
#pragma unroll
                for (int l = 0; l < 5; l++) ha[l] = h * DP_A[s][l];

                for (int i = tid; i < (Dd + 1) * MROWS; i += NT) {
                    int d = i >> 4, r = i & 15;
                    float z;
                    if (d == Dd) {
                        z = tstage;
                    } else {
                        z = sY[d * STRY + r];
#pragma unroll
                        for (int l = 0; l < 5; l++)
                            if (l < s) z += ha[l] * gk[(l * Dd + d) * STRY + r];
                    }
                    *(float2*)(sZd + d * STRD + 2 * r) = make_float2(z, z);
                }
                __syncthreads();

                dense256<Dd + 1, true, true >(W1, b1, sZd,  sH1d, lane, g, r0);
                __syncthreads();
                dense256<Hh,     true, false>(W2, b2, sH1d, sH2,  lane, g, r0);
                __syncthreads();
                dense64out(W3, b3, sH2, gk + s * Dd * STRY, lane, r0d);
                __syncthreads();
            }

            for (int i = tid; i < Dd * MROWS; i += NT) {
                int d = i >> 4, r = i & 15;
                int o = d * STRY + r;
                float acc = (35.f/384.f)     * gk[o]
                          + (500.f/1113.f)   * gk[(2*Dd)*STRY + o]
                          + (125.f/192.f)    * gk[(3*Dd)*STRY + o]
                          + (-2187.f/6784.f) * gk[(4*Dd)*STRY + o]
                          + (11.f/84.f)      * gk[(5*Dd)*STRY + o];
                sY[o] += h * acc;
            }
            __syncthreads();
        }
    }

    for (int i = tid; i < MROWS * Dd; i += NT) {
        int r = i >> 6, d = i & 63;
        out[(rbase + r) * Dd + d] = sY[d * STRY + r];
    }
}

extern "C" void kernel_launch(void* const* d_in, const int* in_sizes, int n_in,
                              void* d_out, int out_size)
{
    (void)in_sizes; (void)n_in; (void)out_size;
    const float* x = (const float*)d_in[0];

    FfjordParams P;
    P.W1[0] = (const float*)d_in[1];  P.b1[0] = (const float*)d_in[2];
    P.W2[0] = (const float*)d_in[3];  P.b2[0] = (const float*)d_in[4];
    P.W3[0] = (const float*)d_in[5];  P.b3[0] = (const float*)d_in[6];
    P.W1[1] = (const float*)d_in[7];  P.b1[1] = (const float*)d_in[8];
    P.W2[1] = (const float*)d_in[9];  P.b2[1] = (const float*)d_in[10];
    P.W3[1] = (const float*)d_in[11]; P.b3[1] = (const float*)d_in[12];

    static_assert(SM_BYTES <= 75 * 1024, "smem budget (3 CTAs/SM)");
    cudaFuncSetAttribute(ffjord_kernel, cudaFuncAttributeMaxDynamicSharedMemorySize, SM_BYTES);

    ffjord_kernel<<<NCTAS, NT, SM_BYTES>>>(x, (float*)d_out, P);
}